// round 13
// baseline (speedup 1.0000x reference)
#include <cuda_runtime.h>
#include <cuda_bf16.h>
#include <cstdint>

#define HDIM 50
#define TLEN 512
#define NB 32
#define NWARP 7
#define NTH (NWARP*32)          // 224
#define NTILE 13                // M-tiles (208 rows)
#define NCTA 128
#define KT0 4                   // phase A k-tiles (K=64, real 52)
#define KT1 7                   // phase B k-tiles (K=112, real 101)
#define GP 36                   // G pitch (floats)
#define BPQ 34                  // B pitch (uint4 words per row)

// ---- smem offsets (bytes) ----
#define OFF_WA0 0
#define SZ_WA0  (NTILE*KT0*2*32*16)      // 53248
#define OFF_WA1 (OFF_WA0+SZ_WA0)
#define SZ_WA1  (NTILE*KT1*2*32*16)      // 93184
#define OFF_BQ0 (OFF_WA1+SZ_WA1)         // 146432, double-buffered
#define SZ_BQ0  (KT0*4*BPQ*16)           // 8704
#define OFF_BQ1 (OFF_BQ0+2*SZ_BQ0)       // 163840, double-buffered
#define SZ_BQ1  (KT1*4*BPQ*16)           // 15232
#define OFF_G   (OFF_BQ1+2*SZ_BQ1)       // 194304
#define SZ_G    (NTILE*16*GP*4)          // 29952
#define SMEM_BYTES (OFF_G+SZ_G)          // 224256

#define B0W (SZ_BQ0/16)
#define B1W (SZ_BQ1/16)
#define B0H (SZ_BQ0/2)
#define B1H (SZ_BQ1/2)

__device__ __forceinline__ float tanha(float z) {
    float r; asm("tanh.approx.f32 %0, %1;" : "=f"(r) : "f"(z)); return r;
}
__device__ __forceinline__ float sigf(float z) {
    return fmaf(0.5f, tanha(0.5f * z), 0.5f);
}
__device__ __forceinline__ unsigned short us16(float f) {
    return __bfloat16_as_ushort(__float2bfloat16(f));
}
__device__ __forceinline__ uint32_t pkbf(float e, float o) {
    return (uint32_t)us16(e) | ((uint32_t)us16(o) << 16);
}
__device__ __forceinline__ float bfhi(float f) {
    return __bfloat162float(__float2bfloat16(f));
}
__device__ __forceinline__ int bidx16(int k, int n) {
    int k2 = k >> 1, kt = k2 >> 3, rr = k2 & 7;
    return ((kt * 4 + (rr & 3)) * BPQ + n) * 8 + (rr >> 2) * 4 + (k & 1);
}
__device__ __forceinline__ void mma_bf16(float d[4], uint32_t a0, uint32_t a1,
                                         uint32_t a2, uint32_t a3,
                                         uint32_t b0, uint32_t b1) {
    asm volatile(
        "mma.sync.aligned.m16n8k16.row.col.f32.bf16.bf16.f32 "
        "{%0,%1,%2,%3}, {%4,%5,%6,%7}, {%8,%9}, {%0,%1,%2,%3};"
        : "+f"(d[0]), "+f"(d[1]), "+f"(d[2]), "+f"(d[3])
        : "r"(a0), "r"(a1), "r"(a2), "r"(a3), "r"(b0), "r"(b1));
}

__global__ void __launch_bounds__(NTH, 1)
lstm_kernel(const float* __restrict__ x,
            const float* __restrict__ w_ih0, const float* __restrict__ w_hh0,
            const float* __restrict__ b_ih0, const float* __restrict__ b_hh0,
            const float* __restrict__ w_ih1, const float* __restrict__ w_hh1,
            const float* __restrict__ b_ih1, const float* __restrict__ b_hh1,
            const float* __restrict__ fc_w,  const float* __restrict__ fc_b,
            float* __restrict__ out) {
    extern __shared__ char sm[];
    uint4* WA0 = (uint4*)(sm + OFF_WA0);
    uint4* WA1 = (uint4*)(sm + OFF_WA1);
    uint4* Bq0 = (uint4*)(sm + OFF_BQ0);
    uint4* Bq1 = (uint4*)(sm + OFF_BQ1);
    unsigned short* B0h = (unsigned short*)(sm + OFF_BQ0);
    unsigned short* B1h = (unsigned short*)(sm + OFF_BQ1);
    float* Gf = (float*)(sm + OFF_G);

    const int tid = threadIdx.x, lane = tid & 31, w = tid >> 5;
    const int g4 = lane >> 2, t4 = lane & 3;
    const int b0g = blockIdx.x * NB;
    const int ntile = (w < 6) ? 2 : 1;      // warps 0-5: tiles 2w,2w+1; warp 6: tile 12
    const int mt0 = (w < 6) ? 2 * w : 12;

    auto wld = [&](int ph, int R, int k) -> float {
        if (R >= 4 * HDIM) return 0.f;
        int u = R >> 2, gate = R & 3, gi = gate * HDIM + u;
        if (ph == 0) {
            if (k < HDIM)      return w_hh0[gi * HDIM + k];
            if (k == HDIM)     return w_ih0[gi];
            if (k == HDIM + 1) return b_ih0[gi] + b_hh0[gi];
            return 0.f;
        } else {
            if (k < HDIM)      return w_ih1[gi * HDIM + k];
            if (k < 2 * HDIM)  return w_hh1[gi * HDIM + k - HDIM];
            if (k == 2 * HDIM) return b_ih1[gi] + b_hh1[gi];
            return 0.f;
        }
    };
    auto wspl = [&](int ph, int R, int k, int term) -> float {
        float f = wld(ph, R, k);
        float fh = bfhi(f);
        return term ? (f - fh) : fh;
    };

    // ---- build A fragments (hi/lo), frag-order packed ----
    for (int i = tid; i < NTILE * (KT0 + KT1) * 2 * 32; i += NTH) {
        int ln = i & 31;
        int rest = i >> 5;
        int term = rest & 1;
        int tile = rest >> 1;
        int ph, mt, kt;
        if (tile < NTILE * KT0) { ph = 0; mt = tile / KT0; kt = tile % KT0; }
        else { int tt = tile - NTILE * KT0; ph = 1; mt = tt / KT1; kt = tt % KT1; }
        int gg = ln >> 2, tt4 = ln & 3;
        int R0 = mt * 16 + gg, R1 = R0 + 8, k0 = kt * 16;
        uint4 v;
        v.x = pkbf(wspl(ph, R0, k0 + 2 * tt4,     term), wspl(ph, R0, k0 + 2 * tt4 + 1, term));
        v.y = pkbf(wspl(ph, R1, k0 + 2 * tt4,     term), wspl(ph, R1, k0 + 2 * tt4 + 1, term));
        v.z = pkbf(wspl(ph, R0, k0 + 2 * tt4 + 8, term), wspl(ph, R0, k0 + 2 * tt4 + 9, term));
        v.w = pkbf(wspl(ph, R1, k0 + 2 * tt4 + 8, term), wspl(ph, R1, k0 + 2 * tt4 + 9, term));
        if (ph == 0) WA0[((mt * KT0 + kt) * 2 + term) * 32 + ln] = v;
        else         WA1[((mt * KT1 + kt) * 2 + term) * 32 + ln] = v;
    }
    // zero all four B buffers (contiguous)
    for (int i = tid; i < (2 * SZ_BQ0 + 2 * SZ_BQ1) / 4; i += NTH)
        ((uint32_t*)(sm + OFF_BQ0))[i] = 0u;
    __syncthreads();
    // bias columns (both buffers) + x(0) -> B0[1], x(1) -> B0[0]
    if (tid < 32) {
        B0h[0 * B0H + bidx16(51, tid)]  = us16(1.0f);
        B0h[1 * B0H + bidx16(51, tid)]  = us16(1.0f);
        B1h[0 * B1H + bidx16(100, tid)] = us16(1.0f);
        B1h[1 * B1H + bidx16(100, tid)] = us16(1.0f);
        float f0 = x[(size_t)(b0g + tid) * TLEN + 0];
        float h0 = bfhi(f0);
        B0h[1 * B0H + bidx16(50, tid)]     = us16(h0);
        B0h[1 * B0H + bidx16(50, tid) + 2] = us16(f0 - h0);
        float f1 = x[(size_t)(b0g + tid) * TLEN + 1];
        float h1 = bfhi(f1);
        B0h[0 * B0H + bidx16(50, tid)]     = us16(h1);
        B0h[0 * B0H + bidx16(50, tid) + 2] = us16(f1 - h1);
    }
    __syncthreads();

    const int ul = lane >> 3;            // unit-local 0..3 within a tile
    const int b4 = (lane & 7) * 4;       // first of 4 batches

    float c0[2][4], c1[2][4], h1v[2][4];
#pragma unroll
    for (int ta = 0; ta < 2; ta++)
#pragma unroll
        for (int j = 0; j < 4; j++) { c0[ta][j] = 0.f; c1[ta][j] = 0.f; h1v[ta][j] = 0.f; }

    // ===== Prologue: phase A only, reads B0[1] -> h0(0) into buf 0 =====
    {
        float d0[2][4][4];
#pragma unroll
        for (int ta = 0; ta < 2; ta++)
#pragma unroll
            for (int nt = 0; nt < 4; nt++)
#pragma unroll
                for (int i2 = 0; i2 < 4; i2++) d0[ta][nt][i2] = 0.f;
#pragma unroll
        for (int kt = 0; kt < KT0; kt++) {
            uint4 bq[4];
#pragma unroll
            for (int nt = 0; nt < 4; nt++)
                bq[nt] = Bq0[1 * B0W + (kt * 4 + t4) * BPQ + nt * 8 + g4];
#pragma unroll
            for (int ta = 0; ta < 2; ta++) if (ta < ntile) {
                int mt = mt0 + ta;
                uint4 Ah = WA0[((mt * KT0 + kt) * 2 + 0) * 32 + lane];
                uint4 Al = WA0[((mt * KT0 + kt) * 2 + 1) * 32 + lane];
#pragma unroll
                for (int nt = 0; nt < 4; nt++) {
                    mma_bf16(d0[ta][nt], Ah.x, Ah.y, Ah.z, Ah.w, bq[nt].x, bq[nt].z);
                    mma_bf16(d0[ta][nt], Ah.x, Ah.y, Ah.z, Ah.w, bq[nt].y, bq[nt].w);
                    mma_bf16(d0[ta][nt], Al.x, Al.y, Al.z, Al.w, bq[nt].x, bq[nt].z);
                }
            }
        }
#pragma unroll
        for (int ta = 0; ta < 2; ta++) if (ta < ntile) {
            float* Gw = Gf + (mt0 + ta) * 16 * GP;
#pragma unroll
            for (int nt = 0; nt < 4; nt++) {
                Gw[g4 * GP + nt * 8 + 2 * t4]           = d0[ta][nt][0];
                Gw[g4 * GP + nt * 8 + 2 * t4 + 1]       = d0[ta][nt][1];
                Gw[(g4 + 8) * GP + nt * 8 + 2 * t4]     = d0[ta][nt][2];
                Gw[(g4 + 8) * GP + nt * 8 + 2 * t4 + 1] = d0[ta][nt][3];
            }
        }
        __syncwarp();
#pragma unroll
        for (int ta = 0; ta < 2; ta++) if (ta < ntile) {
            int mt = mt0 + ta, uu = 4 * mt + ul;
            bool uok = (uu < HDIM);
            float* Gw = Gf + mt * 16 * GP;
            float4 gv0 = *(float4*)(Gw + (4 * ul + 0) * GP + b4);
            float4 gv1 = *(float4*)(Gw + (4 * ul + 1) * GP + b4);
            float4 gv2 = *(float4*)(Gw + (4 * ul + 2) * GP + b4);
            float4 gv3 = *(float4*)(Gw + (4 * ul + 3) * GP + b4);
            if (uok) {
                float* pi = (float*)&gv0; float* pf = (float*)&gv1;
                float* pg = (float*)&gv2; float* po = (float*)&gv3;
#pragma unroll
                for (int j = 0; j < 4; j++) {
                    float ig = sigf(pi[j]), fg = sigf(pf[j]);
                    float gg = tanha(pg[j]), og = sigf(po[j]);
                    c0[ta][j] = fmaf(fg, c0[ta][j], ig * gg);
                    float hn = og * tanha(c0[ta][j]);
                    float hh = bfhi(hn);
                    unsigned short hb = us16(hn), lb = us16(hn - hh);
                    int i0 = bidx16(uu, b4 + j);
                    B0h[0 * B0H + i0] = hb; B0h[0 * B0H + i0 + 2] = lb;
                    B1h[0 * B1H + i0] = hb; B1h[0 * B1H + i0 + 2] = lb;
                }
            }
        }
    }
    __syncthreads();

    // ===== Fused main loop: iteration i computes G0(i+1) and G1(i), ONE barrier =====
#pragma unroll 1
    for (int i = 0; i < TLEN - 1; i++) {
        const int cur = i & 1, nxt = cur ^ 1;

        float xv = 0.f;
        if (w == 6 && (i + 2) < TLEN)
            xv = x[(size_t)(b0g + lane) * TLEN + (i + 2)];

        float d0[2][4][4], d1[2][4][4];
#pragma unroll
        for (int ta = 0; ta < 2; ta++)
#pragma unroll
            for (int nt = 0; nt < 4; nt++)
#pragma unroll
                for (int i2 = 0; i2 < 4; i2++) { d0[ta][nt][i2] = 0.f; d1[ta][nt][i2] = 0.f; }

        // --- phase A MMAs: B loaded once, reused for both tiles ---
#pragma unroll
        for (int kt = 0; kt < KT0; kt++) {
            uint4 bq[4];
#pragma unroll
            for (int nt = 0; nt < 4; nt++)
                bq[nt] = Bq0[cur * B0W + (kt * 4 + t4) * BPQ + nt * 8 + g4];
#pragma unroll
            for (int ta = 0; ta < 2; ta++) if (ta < ntile) {
                int mt = mt0 + ta;
                uint4 Ah = WA0[((mt * KT0 + kt) * 2 + 0) * 32 + lane];
                uint4 Al = WA0[((mt * KT0 + kt) * 2 + 1) * 32 + lane];
#pragma unroll
                for (int nt = 0; nt < 4; nt++) {
                    mma_bf16(d0[ta][nt], Ah.x, Ah.y, Ah.z, Ah.w, bq[nt].x, bq[nt].z);
                    mma_bf16(d0[ta][nt], Ah.x, Ah.y, Ah.z, Ah.w, bq[nt].y, bq[nt].w);
                    mma_bf16(d0[ta][nt], Al.x, Al.y, Al.z, Al.w, bq[nt].x, bq[nt].z);
                }
            }
        }
        // --- phase B MMAs ---
#pragma unroll
        for (int kt = 0; kt < KT1; kt++) {
            uint4 bq[4];
#pragma unroll
            for (int nt = 0; nt < 4; nt++)
                bq[nt] = Bq1[cur * B1W + (kt * 4 + t4) * BPQ + nt * 8 + g4];
#pragma unroll
            for (int ta = 0; ta < 2; ta++) if (ta < ntile) {
                int mt = mt0 + ta;
                uint4 Ah = WA1[((mt * KT1 + kt) * 2 + 0) * 32 + lane];
                uint4 Al = WA1[((mt * KT1 + kt) * 2 + 1) * 32 + lane];
#pragma unroll
                for (int nt = 0; nt < 4; nt++) {
                    mma_bf16(d1[ta][nt], Ah.x, Ah.y, Ah.z, Ah.w, bq[nt].x, bq[nt].z);
                    mma_bf16(d1[ta][nt], Ah.x, Ah.y, Ah.z, Ah.w, bq[nt].y, bq[nt].w);
                    mma_bf16(d1[ta][nt], Al.x, Al.y, Al.z, Al.w, bq[nt].x, bq[nt].z);
                }
            }
        }

        // --- epilogue 0: h0(i+1) -> B0[nxt], B1[nxt] ---
#pragma unroll
        for (int ta = 0; ta < 2; ta++) if (ta < ntile) {
            float* Gw = Gf + (mt0 + ta) * 16 * GP;
#pragma unroll
            for (int nt = 0; nt < 4; nt++) {
                Gw[g4 * GP + nt * 8 + 2 * t4]           = d0[ta][nt][0];
                Gw[g4 * GP + nt * 8 + 2 * t4 + 1]       = d0[ta][nt][1];
                Gw[(g4 + 8) * GP + nt * 8 + 2 * t4]     = d0[ta][nt][2];
                Gw[(g4 + 8) * GP + nt * 8 + 2 * t4 + 1] = d0[ta][nt][3];
            }
        }
        __syncwarp();
#pragma unroll
        for (int ta = 0; ta < 2; ta++) if (ta < ntile) {
            int mt = mt0 + ta, uu = 4 * mt + ul;
            bool uok = (uu < HDIM);
            float* Gw = Gf + mt * 16 * GP;
            float4 gv0 = *(float4*)(Gw + (4 * ul + 0) * GP + b4);
            float4 gv1 = *(float4*)(Gw + (4 * ul + 1) * GP + b4);
            float4 gv2 = *(float4*)(Gw + (4 * ul + 2) * GP + b4);
            float4 gv3 = *(float4*)(Gw + (4 * ul + 3) * GP + b4);
            if (uok) {
                float* pi = (float*)&gv0; float* pf = (float*)&gv1;
                float* pg = (float*)&gv2; float* po = (float*)&gv3;
#pragma unroll
                for (int j = 0; j < 4; j++) {
                    float ig = sigf(pi[j]), fg = sigf(pf[j]);
                    float gg = tanha(pg[j]), og = sigf(po[j]);
                    c0[ta][j] = fmaf(fg, c0[ta][j], ig * gg);
                    float hn = og * tanha(c0[ta][j]);
                    float hh = bfhi(hn);
                    unsigned short hb = us16(hn), lb = us16(hn - hh);
                    int i0 = bidx16(uu, b4 + j);
                    B0h[nxt * B0H + i0] = hb; B0h[nxt * B0H + i0 + 2] = lb;
                    B1h[nxt * B1H + i0] = hb; B1h[nxt * B1H + i0 + 2] = lb;
                }
            }
        }
        __syncwarp();
        // --- epilogue 1: h1(i) -> B1[nxt] ---
#pragma unroll
        for (int ta = 0; ta < 2; ta++) if (ta < ntile) {
            float* Gw = Gf + (mt0 + ta) * 16 * GP;
#pragma unroll
            for (int nt = 0; nt < 4; nt++) {
                Gw[g4 * GP + nt * 8 + 2 * t4]           = d1[ta][nt][0];
                Gw[g4 * GP + nt * 8 + 2 * t4 + 1]       = d1[ta][nt][1];
                Gw[(g4 + 8) * GP + nt * 8 + 2 * t4]     = d1[ta][nt][2];
                Gw[(g4 + 8) * GP + nt * 8 + 2 * t4 + 1] = d1[ta][nt][3];
            }
        }
        __syncwarp();
#pragma unroll
        for (int ta = 0; ta < 2; ta++) if (ta < ntile) {
            int mt = mt0 + ta, uu = 4 * mt + ul;
            bool uok = (uu < HDIM);
            float* Gw = Gf + mt * 16 * GP;
            float4 gv0 = *(float4*)(Gw + (4 * ul + 0) * GP + b4);
            float4 gv1 = *(float4*)(Gw + (4 * ul + 1) * GP + b4);
            float4 gv2 = *(float4*)(Gw + (4 * ul + 2) * GP + b4);
            float4 gv3 = *(float4*)(Gw + (4 * ul + 3) * GP + b4);
            if (uok) {
                float* pi = (float*)&gv0; float* pf = (float*)&gv1;
                float* pg = (float*)&gv2; float* po = (float*)&gv3;
#pragma unroll
                for (int j = 0; j < 4; j++) {
                    float ig = sigf(pi[j]), fg = sigf(pf[j]);
                    float gg = tanha(pg[j]), og = sigf(po[j]);
                    c1[ta][j] = fmaf(fg, c1[ta][j], ig * gg);
                    float hn = og * tanha(c1[ta][j]);
                    h1v[ta][j] = hn;
                    float hh = bfhi(hn);
                    unsigned short hb = us16(hn), lb = us16(hn - hh);
                    int i1 = bidx16(50 + uu, b4 + j);
                    B1h[nxt * B1H + i1] = hb; B1h[nxt * B1H + i1 + 2] = lb;
                }
            }
        }
        if (w == 6 && (i + 2) < TLEN) {
            float fh = bfhi(xv);
            B0h[nxt * B0H + bidx16(50, lane)]     = us16(fh);
            B0h[nxt * B0H + bidx16(50, lane) + 2] = us16(xv - fh);
        }
        __syncthreads();
    }

    // ===== Tail: G1(511) from B1[1] -> h1(511) =====
    {
        const int cur = (TLEN - 1) & 1;   // 1
        float d1[2][4][4];
#pragma unroll
        for (int ta = 0; ta < 2; ta++)
#pragma unroll
            for (int nt = 0; nt < 4; nt++)
#pragma unroll
                for (int i2 = 0; i2 < 4; i2++) d1[ta][nt][i2] = 0.f;
#pragma unroll
        for (int kt = 0; kt < KT1; kt++) {
            uint4 bq[4];
#pragma unroll
            for (int nt = 0; nt < 4; nt++)
                bq[nt] = Bq1[cur * B1W + (kt * 4 + t4) * BPQ + nt * 8 + g4];
#pragma unroll
            for (int ta = 0; ta < 2; ta++) if (ta < ntile) {
                int mt = mt0 + ta;
                uint4 Ah = WA1[((mt * KT1 + kt) * 2 + 0) * 32 + lane];
                uint4 Al = WA1[((mt * KT1 + kt) * 2 + 1) * 32 + lane];
#pragma unroll
                for (int nt = 0; nt < 4; nt++) {
                    mma_bf16(d1[ta][nt], Ah.x, Ah.y, Ah.z, Ah.w, bq[nt].x, bq[nt].z);
                    mma_bf16(d1[ta][nt], Ah.x, Ah.y, Ah.z, Ah.w, bq[nt].y, bq[nt].w);
                    mma_bf16(d1[ta][nt], Al.x, Al.y, Al.z, Al.w, bq[nt].x, bq[nt].z);
                }
            }
        }
#pragma unroll
        for (int ta = 0; ta < 2; ta++) if (ta < ntile) {
            float* Gw = Gf + (mt0 + ta) * 16 * GP;
#pragma unroll
            for (int nt = 0; nt < 4; nt++) {
                Gw[g4 * GP + nt * 8 + 2 * t4]           = d1[ta][nt][0];
                Gw[g4 * GP + nt * 8 + 2 * t4 + 1]       = d1[ta][nt][1];
                Gw[(g4 + 8) * GP + nt * 8 + 2 * t4]     = d1[ta][nt][2];
                Gw[(g4 + 8) * GP + nt * 8 + 2 * t4 + 1] = d1[ta][nt][3];
            }
        }
        __syncwarp();
#pragma unroll
        for (int ta = 0; ta < 2; ta++) if (ta < ntile) {
            int mt = mt0 + ta, uu = 4 * mt + ul;
            bool uok = (uu < HDIM);
            float* Gw = Gf + mt * 16 * GP;
            float4 gv0 = *(float4*)(Gw + (4 * ul + 0) * GP + b4);
            float4 gv1 = *(float4*)(Gw + (4 * ul + 1) * GP + b4);
            float4 gv2 = *(float4*)(Gw + (4 * ul + 2) * GP + b4);
            float4 gv3 = *(float4*)(Gw + (4 * ul + 3) * GP + b4);
            if (uok) {
                float* pi = (float*)&gv0; float* pf = (float*)&gv1;
                float* pg = (float*)&gv2; float* po = (float*)&gv3;
#pragma unroll
                for (int j = 0; j < 4; j++) {
                    float ig = sigf(pi[j]), fg = sigf(pf[j]);
                    float gg = tanha(pg[j]), og = sigf(po[j]);
                    c1[ta][j] = fmaf(fg, c1[ta][j], ig * gg);
                    h1v[ta][j] = og * tanha(c1[ta][j]);
                }
            }
        }
    }
    __syncthreads();

    // ===== FC epilogue: out[b] = fc_w . h1(511)[b] + fc_b =====
#pragma unroll
    for (int ta = 0; ta < 2; ta++) if (ta < ntile) {
        int uu = 4 * (mt0 + ta) + ul;
        if (uu < HDIM) {
            float fw = fc_w[uu];
#pragma unroll
            for (int j = 0; j < 4; j++) Gf[uu * 32 + b4 + j] = fw * h1v[ta][j];
        }
    }
    __syncthreads();
    if (tid < 32) {
        float s = fc_b[0];
#pragma unroll 10
        for (int k = 0; k < HDIM; k++) s += Gf[k * 32 + tid];
        out[b0g + tid] = s;
    }
}

extern "C" void kernel_launch(void* const* d_in, const int* in_sizes, int n_in,
                              void* d_out, int out_size) {
    const float* x     = (const float*)d_in[0];
    const float* w_ih0 = (const float*)d_in[1];
    const float* w_hh0 = (const float*)d_in[2];
    const float* b_ih0 = (const float*)d_in[3];
    const float* b_hh0 = (const float*)d_in[4];
    const float* w_ih1 = (const float*)d_in[5];
    const float* w_hh1 = (const float*)d_in[6];
    const float* b_ih1 = (const float*)d_in[7];
    const float* b_hh1 = (const float*)d_in[8];
    const float* fc_w  = (const float*)d_in[9];
    const float* fc_b  = (const float*)d_in[10];
    float* out = (float*)d_out;

    cudaFuncSetAttribute(lstm_kernel, cudaFuncAttributeMaxDynamicSharedMemorySize,
                         SMEM_BYTES);
    lstm_kernel<<<NCTA, NTH, SMEM_BYTES>>>(x, w_ih0, w_hh0, b_ih0, b_hh0,
                                           w_ih1, w_hh1, b_ih1, b_hh1,
                                           fc_w, fc_b, out);
}

// round 14
// speedup vs baseline: 1.1338x; 1.1338x over previous
#include <cuda_runtime.h>
#include <cuda_bf16.h>
#include <cstdint>

#define HDIM 50
#define TLEN 512
#define NB 32
#define NWARP 26
#define NTH (NWARP*32)          // 832
#define NTILE 13                // M-tiles (208 rows)
#define NCTA 128
#define KT0 4                   // phase A k-tiles (K=64, real 52)
#define KT1 7                   // phase B k-tiles (K=112, real 101)
#define GP 36                   // G pitch (floats)
#define BPQ 34                  // B pitch (uint4 words per row)

// ---- smem offsets (bytes) ----
#define OFF_WA0 0
#define SZ_WA0  (NTILE*KT0*2*32*16)      // 53248
#define OFF_WA1 (OFF_WA0+SZ_WA0)
#define SZ_WA1  (NTILE*KT1*2*32*16)      // 93184
#define OFF_BQ0 (OFF_WA1+SZ_WA1)         // 146432, double-buffered
#define SZ_BQ0  (KT0*4*BPQ*16)           // 8704
#define OFF_BQ1 (OFF_BQ0+2*SZ_BQ0)       // 163840, double-buffered
#define SZ_BQ1  (KT1*4*BPQ*16)           // 15232
#define OFF_G   (OFF_BQ1+2*SZ_BQ1)       // 194304
#define SZ_G    (NTILE*16*GP*4)          // 29952
#define SMEM_BYTES (OFF_G+SZ_G)          // 224256

#define B0W (SZ_BQ0/16)
#define B1W (SZ_BQ1/16)
#define B0H (SZ_BQ0/2)
#define B1H (SZ_BQ1/2)

__device__ __forceinline__ float tanha(float z) {
    float r; asm("tanh.approx.f32 %0, %1;" : "=f"(r) : "f"(z)); return r;
}
__device__ __forceinline__ float sigf(float z) {
    return fmaf(0.5f, tanha(0.5f * z), 0.5f);
}
__device__ __forceinline__ unsigned short us16(float f) {
    return __bfloat16_as_ushort(__float2bfloat16(f));
}
__device__ __forceinline__ uint32_t pkbf(float e, float o) {
    return (uint32_t)us16(e) | ((uint32_t)us16(o) << 16);
}
__device__ __forceinline__ float bfhi(float f) {
    return __bfloat162float(__float2bfloat16(f));
}
__device__ __forceinline__ int bidx16(int k, int n) {
    int k2 = k >> 1, kt = k2 >> 3, rr = k2 & 7;
    return ((kt * 4 + (rr & 3)) * BPQ + n) * 8 + (rr >> 2) * 4 + (k & 1);
}
__device__ __forceinline__ void mma_bf16(float d[4], uint32_t a0, uint32_t a1,
                                         uint32_t a2, uint32_t a3,
                                         uint32_t b0, uint32_t b1) {
    asm volatile(
        "mma.sync.aligned.m16n8k16.row.col.f32.bf16.bf16.f32 "
        "{%0,%1,%2,%3}, {%4,%5,%6,%7}, {%8,%9}, {%0,%1,%2,%3};"
        : "+f"(d[0]), "+f"(d[1]), "+f"(d[2]), "+f"(d[3])
        : "r"(a0), "r"(a1), "r"(a2), "r"(a3), "r"(b0), "r"(b1));
}

__global__ void __launch_bounds__(NTH, 1)
lstm_kernel(const float* __restrict__ x,
            const float* __restrict__ w_ih0, const float* __restrict__ w_hh0,
            const float* __restrict__ b_ih0, const float* __restrict__ b_hh0,
            const float* __restrict__ w_ih1, const float* __restrict__ w_hh1,
            const float* __restrict__ b_ih1, const float* __restrict__ b_hh1,
            const float* __restrict__ fc_w,  const float* __restrict__ fc_b,
            float* __restrict__ out) {
    extern __shared__ char sm[];
    uint4* WA0 = (uint4*)(sm + OFF_WA0);
    uint4* WA1 = (uint4*)(sm + OFF_WA1);
    uint4* Bq0 = (uint4*)(sm + OFF_BQ0);
    uint4* Bq1 = (uint4*)(sm + OFF_BQ1);
    unsigned short* B0h = (unsigned short*)(sm + OFF_BQ0);
    unsigned short* B1h = (unsigned short*)(sm + OFF_BQ1);
    float* Gf = (float*)(sm + OFF_G);

    const int tid = threadIdx.x, lane = tid & 31, w = tid >> 5;
    const int g4 = lane >> 2, t4 = lane & 3;
    const int b0g = blockIdx.x * NB;
    const int mt = w >> 1;               // M-tile for this warp
    const int half = w & 1;              // N-half (batches 16*half .. +15)
    const int nt0 = 2 * half;            // first n-subtile

    auto wld = [&](int ph, int R, int k) -> float {
        if (R >= 4 * HDIM) return 0.f;
        int u = R >> 2, gate = R & 3, gi = gate * HDIM + u;
        if (ph == 0) {
            if (k < HDIM)      return w_hh0[gi * HDIM + k];
            if (k == HDIM)     return w_ih0[gi];
            if (k == HDIM + 1) return b_ih0[gi] + b_hh0[gi];
            return 0.f;
        } else {
            if (k < HDIM)      return w_ih1[gi * HDIM + k];
            if (k < 2 * HDIM)  return w_hh1[gi * HDIM + k - HDIM];
            if (k == 2 * HDIM) return b_ih1[gi] + b_hh1[gi];
            return 0.f;
        }
    };
    auto wspl = [&](int ph, int R, int k, int term) -> float {
        float f = wld(ph, R, k);
        float fh = bfhi(f);
        return term ? (f - fh) : fh;
    };

    // ---- build A fragments (hi/lo), frag-order packed ----
    for (int i = tid; i < NTILE * (KT0 + KT1) * 2 * 32; i += NTH) {
        int ln = i & 31;
        int rest = i >> 5;
        int term = rest & 1;
        int tile = rest >> 1;
        int ph, mtt, kt;
        if (tile < NTILE * KT0) { ph = 0; mtt = tile / KT0; kt = tile % KT0; }
        else { int tt = tile - NTILE * KT0; ph = 1; mtt = tt / KT1; kt = tt % KT1; }
        int gg = ln >> 2, tt4 = ln & 3;
        int R0 = mtt * 16 + gg, R1 = R0 + 8, k0 = kt * 16;
        uint4 v;
        v.x = pkbf(wspl(ph, R0, k0 + 2 * tt4,     term), wspl(ph, R0, k0 + 2 * tt4 + 1, term));
        v.y = pkbf(wspl(ph, R1, k0 + 2 * tt4,     term), wspl(ph, R1, k0 + 2 * tt4 + 1, term));
        v.z = pkbf(wspl(ph, R0, k0 + 2 * tt4 + 8, term), wspl(ph, R0, k0 + 2 * tt4 + 9, term));
        v.w = pkbf(wspl(ph, R1, k0 + 2 * tt4 + 8, term), wspl(ph, R1, k0 + 2 * tt4 + 9, term));
        if (ph == 0) WA0[((mtt * KT0 + kt) * 2 + term) * 32 + ln] = v;
        else         WA1[((mtt * KT1 + kt) * 2 + term) * 32 + ln] = v;
    }
    // zero all four B buffers (contiguous)
    for (int i = tid; i < (2 * SZ_BQ0 + 2 * SZ_BQ1) / 4; i += NTH)
        ((uint32_t*)(sm + OFF_BQ0))[i] = 0u;
    __syncthreads();
    // bias columns (both buffers) + x(0) -> B0[1], x(1) -> B0[0]
    if (tid < 32) {
        B0h[0 * B0H + bidx16(51, tid)]  = us16(1.0f);
        B0h[1 * B0H + bidx16(51, tid)]  = us16(1.0f);
        B1h[0 * B1H + bidx16(100, tid)] = us16(1.0f);
        B1h[1 * B1H + bidx16(100, tid)] = us16(1.0f);
        float f0 = x[(size_t)(b0g + tid) * TLEN + 0];
        float h0 = bfhi(f0);
        B0h[1 * B0H + bidx16(50, tid)]     = us16(h0);
        B0h[1 * B0H + bidx16(50, tid) + 2] = us16(f0 - h0);
        float f1 = x[(size_t)(b0g + tid) * TLEN + 1];
        float h1 = bfhi(f1);
        B0h[0 * B0H + bidx16(50, tid)]     = us16(h1);
        B0h[0 * B0H + bidx16(50, tid) + 2] = us16(f1 - h1);
    }
    __syncthreads();

    const int ul = lane >> 3;            // unit-local 0..3 within the tile
    const int bb = (lane & 7) * 2;       // batch pair within the 16-batch half
    const int uu = 4 * mt + ul;
    const bool uok = (uu < HDIM);
    const int bcol = 16 * half + bb;     // first batch column (within 32)
    float* Gw = Gf + mt * 16 * GP;

    float c0[2], c1[2], h1v[2];
#pragma unroll
    for (int j = 0; j < 2; j++) { c0[j] = 0.f; c1[j] = 0.f; h1v[j] = 0.f; }

    // ===== Prologue: phase A only, reads B0[1] -> h0(0) into buf 0 =====
    {
        float d0[2][4];
#pragma unroll
        for (int na = 0; na < 2; na++)
#pragma unroll
            for (int i2 = 0; i2 < 4; i2++) d0[na][i2] = 0.f;
#pragma unroll
        for (int kt = 0; kt < KT0; kt++) {
            uint4 Ah = WA0[((mt * KT0 + kt) * 2 + 0) * 32 + lane];
            uint4 Al = WA0[((mt * KT0 + kt) * 2 + 1) * 32 + lane];
#pragma unroll
            for (int na = 0; na < 2; na++) {
                uint4 bq = Bq0[1 * B0W + (kt * 4 + t4) * BPQ + (nt0 + na) * 8 + g4];
                mma_bf16(d0[na], Ah.x, Ah.y, Ah.z, Ah.w, bq.x, bq.z);
                mma_bf16(d0[na], Ah.x, Ah.y, Ah.z, Ah.w, bq.y, bq.w);
                mma_bf16(d0[na], Al.x, Al.y, Al.z, Al.w, bq.x, bq.z);
            }
        }
#pragma unroll
        for (int na = 0; na < 2; na++) {
            int nt = nt0 + na;
            Gw[g4 * GP + nt * 8 + 2 * t4]           = d0[na][0];
            Gw[g4 * GP + nt * 8 + 2 * t4 + 1]       = d0[na][1];
            Gw[(g4 + 8) * GP + nt * 8 + 2 * t4]     = d0[na][2];
            Gw[(g4 + 8) * GP + nt * 8 + 2 * t4 + 1] = d0[na][3];
        }
        __syncwarp();
        float2 gv0 = *(float2*)(Gw + (4 * ul + 0) * GP + bcol);
        float2 gv1 = *(float2*)(Gw + (4 * ul + 1) * GP + bcol);
        float2 gv2 = *(float2*)(Gw + (4 * ul + 2) * GP + bcol);
        float2 gv3 = *(float2*)(Gw + (4 * ul + 3) * GP + bcol);
        if (uok) {
            float* pi = (float*)&gv0; float* pf = (float*)&gv1;
            float* pg = (float*)&gv2; float* po = (float*)&gv3;
#pragma unroll
            for (int j = 0; j < 2; j++) {
                float ig = sigf(pi[j]), fg = sigf(pf[j]);
                float gg = tanha(pg[j]), og = sigf(po[j]);
                c0[j] = fmaf(fg, c0[j], ig * gg);
                float hn = og * tanha(c0[j]);
                float hh = bfhi(hn);
                unsigned short hb = us16(hn), lb = us16(hn - hh);
                int i0 = bidx16(uu, bcol + j);
                B0h[0 * B0H + i0] = hb; B0h[0 * B0H + i0 + 2] = lb;
                B1h[0 * B1H + i0] = hb; B1h[0 * B1H + i0 + 2] = lb;
            }
        }
    }
    __syncthreads();

    // ===== Fused main loop: iteration i computes G0(i+1) and G1(i), ONE barrier =====
#pragma unroll 1
    for (int i = 0; i < TLEN - 1; i++) {
        const int cur = i & 1, nxt = cur ^ 1;

        float xv = 0.f;
        if (w == 25 && (i + 2) < TLEN)
            xv = x[(size_t)(b0g + lane) * TLEN + (i + 2)];

        float d0[2][4], d1[2][4];
#pragma unroll
        for (int na = 0; na < 2; na++)
#pragma unroll
            for (int i2 = 0; i2 < 4; i2++) { d0[na][i2] = 0.f; d1[na][i2] = 0.f; }

        // --- all 66 MMAs for this warp back-to-back ---
#pragma unroll
        for (int kt = 0; kt < KT0; kt++) {
            uint4 Ah = WA0[((mt * KT0 + kt) * 2 + 0) * 32 + lane];
            uint4 Al = WA0[((mt * KT0 + kt) * 2 + 1) * 32 + lane];
#pragma unroll
            for (int na = 0; na < 2; na++) {
                uint4 bq = Bq0[cur * B0W + (kt * 4 + t4) * BPQ + (nt0 + na) * 8 + g4];
                mma_bf16(d0[na], Ah.x, Ah.y, Ah.z, Ah.w, bq.x, bq.z);
                mma_bf16(d0[na], Ah.x, Ah.y, Ah.z, Ah.w, bq.y, bq.w);
                mma_bf16(d0[na], Al.x, Al.y, Al.z, Al.w, bq.x, bq.z);
            }
        }
#pragma unroll
        for (int kt = 0; kt < KT1; kt++) {
            uint4 Ah = WA1[((mt * KT1 + kt) * 2 + 0) * 32 + lane];
            uint4 Al = WA1[((mt * KT1 + kt) * 2 + 1) * 32 + lane];
#pragma unroll
            for (int na = 0; na < 2; na++) {
                uint4 bq = Bq1[cur * B1W + (kt * 4 + t4) * BPQ + (nt0 + na) * 8 + g4];
                mma_bf16(d1[na], Ah.x, Ah.y, Ah.z, Ah.w, bq.x, bq.z);
                mma_bf16(d1[na], Ah.x, Ah.y, Ah.z, Ah.w, bq.y, bq.w);
                mma_bf16(d1[na], Al.x, Al.y, Al.z, Al.w, bq.x, bq.z);
            }
        }

        // --- epilogue 0: h0(i+1) -> B0[nxt], B1[nxt] ---
#pragma unroll
        for (int na = 0; na < 2; na++) {
            int nt = nt0 + na;
            Gw[g4 * GP + nt * 8 + 2 * t4]           = d0[na][0];
            Gw[g4 * GP + nt * 8 + 2 * t4 + 1]       = d0[na][1];
            Gw[(g4 + 8) * GP + nt * 8 + 2 * t4]     = d0[na][2];
            Gw[(g4 + 8) * GP + nt * 8 + 2 * t4 + 1] = d0[na][3];
        }
        __syncwarp();
        {
            float2 gv0 = *(float2*)(Gw + (4 * ul + 0) * GP + bcol);
            float2 gv1 = *(float2*)(Gw + (4 * ul + 1) * GP + bcol);
            float2 gv2 = *(float2*)(Gw + (4 * ul + 2) * GP + bcol);
            float2 gv3 = *(float2*)(Gw + (4 * ul + 3) * GP + bcol);
            __syncwarp();
            if (uok) {
                float* pi = (float*)&gv0; float* pf = (float*)&gv1;
                float* pg = (float*)&gv2; float* po = (float*)&gv3;
#pragma unroll
                for (int j = 0; j < 2; j++) {
                    float ig = sigf(pi[j]), fg = sigf(pf[j]);
                    float gg = tanha(pg[j]), og = sigf(po[j]);
                    c0[j] = fmaf(fg, c0[j], ig * gg);
                    float hn = og * tanha(c0[j]);
                    float hh = bfhi(hn);
                    unsigned short hb = us16(hn), lb = us16(hn - hh);
                    int i0 = bidx16(uu, bcol + j);
                    B0h[nxt * B0H + i0] = hb; B0h[nxt * B0H + i0 + 2] = lb;
                    B1h[nxt * B1H + i0] = hb; B1h[nxt * B1H + i0 + 2] = lb;
                }
            }
        }
        // --- epilogue 1: h1(i) -> B1[nxt] ---
#pragma unroll
        for (int na = 0; na < 2; na++) {
            int nt = nt0 + na;
            Gw[g4 * GP + nt * 8 + 2 * t4]           = d1[na][0];
            Gw[g4 * GP + nt * 8 + 2 * t4 + 1]       = d1[na][1];
            Gw[(g4 + 8) * GP + nt * 8 + 2 * t4]     = d1[na][2];
            Gw[(g4 + 8) * GP + nt * 8 + 2 * t4 + 1] = d1[na][3];
        }
        __syncwarp();
        {
            float2 gv0 = *(float2*)(Gw + (4 * ul + 0) * GP + bcol);
            float2 gv1 = *(float2*)(Gw + (4 * ul + 1) * GP + bcol);
            float2 gv2 = *(float2*)(Gw + (4 * ul + 2) * GP + bcol);
            float2 gv3 = *(float2*)(Gw + (4 * ul + 3) * GP + bcol);
            __syncwarp();
            if (uok) {
                float* pi = (float*)&gv0; float* pf = (float*)&gv1;
                float* pg = (float*)&gv2; float* po = (float*)&gv3;
#pragma unroll
                for (int j = 0; j < 2; j++) {
                    float ig = sigf(pi[j]), fg = sigf(pf[j]);
                    float gg = tanha(pg[j]), og = sigf(po[j]);
                    c1[j] = fmaf(fg, c1[j], ig * gg);
                    float hn = og * tanha(c1[j]);
                    h1v[j] = hn;
                    float hh = bfhi(hn);
                    unsigned short hb = us16(hn), lb = us16(hn - hh);
                    int i1 = bidx16(50 + uu, bcol + j);
                    B1h[nxt * B1H + i1] = hb; B1h[nxt * B1H + i1 + 2] = lb;
                }
            }
        }
        if (w == 25 && (i + 2) < TLEN) {
            float fh = bfhi(xv);
            B0h[nxt * B0H + bidx16(50, lane)]     = us16(fh);
            B0h[nxt * B0H + bidx16(50, lane) + 2] = us16(xv - fh);
        }
        __syncthreads();
    }

    // ===== Tail: G1(511) from B1[1] -> h1(511) =====
    {
        const int cur = (TLEN - 1) & 1;   // 1
        float d1[2][4];
#pragma unroll
        for (int na = 0; na < 2; na++)
#pragma unroll
            for (int i2 = 0; i2 < 4; i2++) d1[na][i2] = 0.f;
#pragma unroll
        for (int kt = 0; kt < KT1; kt++) {
            uint4 Ah = WA1[((mt * KT1 + kt) * 2 + 0) * 32 + lane];
            uint4 Al = WA1[((mt * KT1 + kt) * 2 + 1) * 32 + lane];
#pragma unroll
            for (int na = 0; na < 2; na++) {
                uint4 bq = Bq1[cur * B1W + (kt * 4 + t4) * BPQ + (nt0 + na) * 8 + g4];
                mma_bf16(d1[na], Ah.x, Ah.y, Ah.z, Ah.w, bq.x, bq.z);
                mma_bf16(d1[na], Ah.x, Ah.y, Ah.z, Ah.w, bq.y, bq.w);
                mma_bf16(d1[na], Al.x, Al.y, Al.z, Al.w, bq.x, bq.z);
            }
        }
#pragma unroll
        for (int na = 0; na < 2; na++) {
            int nt = nt0 + na;
            Gw[g4 * GP + nt * 8 + 2 * t4]           = d1[na][0];
            Gw[g4 * GP + nt * 8 + 2 * t4 + 1]       = d1[na][1];
            Gw[(g4 + 8) * GP + nt * 8 + 2 * t4]     = d1[na][2];
            Gw[(g4 + 8) * GP + nt * 8 + 2 * t4 + 1] = d1[na][3];
        }
        __syncwarp();
        float2 gv0 = *(float2*)(Gw + (4 * ul + 0) * GP + bcol);
        float2 gv1 = *(float2*)(Gw + (4 * ul + 1) * GP + bcol);
        float2 gv2 = *(float2*)(Gw + (4 * ul + 2) * GP + bcol);
        float2 gv3 = *(float2*)(Gw + (4 * ul + 3) * GP + bcol);
        __syncwarp();
        if (uok) {
            float* pi = (float*)&gv0; float* pf = (float*)&gv1;
            float* pg = (float*)&gv2; float* po = (float*)&gv3;
#pragma unroll
            for (int j = 0; j < 2; j++) {
                float ig = sigf(pi[j]), fg = sigf(pf[j]);
                float gg = tanha(pg[j]), og = sigf(po[j]);
                c1[j] = fmaf(fg, c1[j], ig * gg);
                h1v[j] = og * tanha(c1[j]);
            }
        }
    }
    __syncthreads();

    // ===== FC epilogue: out[b] = fc_w . h1(511)[b] + fc_b =====
    if (uok) {
        float fw = fc_w[uu];
#pragma unroll
        for (int j = 0; j < 2; j++) Gf[uu * 32 + bcol + j] = fw * h1v[j];
    }
    __syncthreads();
    if (tid < 32) {
        float s = fc_b[0];
#pragma unroll 10
        for (int k = 0; k < HDIM; k++) s += Gf[k * 32 + tid];
        out[b0g + tid] = s;
    }
}

extern "C" void kernel_launch(void* const* d_in, const int* in_sizes, int n_in,
                              void* d_out, int out_size) {
    const float* x     = (const float*)d_in[0];
    const float* w_ih0 = (const float*)d_in[1];
    const float* w_hh0 = (const float*)d_in[2];
    const float* b_ih0 = (const float*)d_in[3];
    const float* b_hh0 = (const float*)d_in[4];
    const float* w_ih1 = (const float*)d_in[5];
    const float* w_hh1 = (const float*)d_in[6];
    const float* b_ih1 = (const float*)d_in[7];
    const float* b_hh1 = (const float*)d_in[8];
    const float* fc_w  = (const float*)d_in[9];
    const float* fc_b  = (const float*)d_in[10];
    float* out = (float*)d_out;

    cudaFuncSetAttribute(lstm_kernel, cudaFuncAttributeMaxDynamicSharedMemorySize,
                         SMEM_BYTES);
    lstm_kernel<<<NCTA, NTH, SMEM_BYTES>>>(x, w_ih0, w_hh0, b_ih0, b_hh0,
                                           w_ih1, w_hh1, b_ih1, b_hh1,
                                           fc_w, fc_b, out);
}

// round 15
// speedup vs baseline: 1.2520x; 1.1042x over previous
#include <cuda_runtime.h>
#include <cuda_bf16.h>
#include <cstdint>

#define HDIM 50
#define TLEN 512
#define NB 32
#define NWARP 26
#define NTH (NWARP*32)          // 832
#define NTILE 13                // M-tiles (208 rows)
#define NCTA 128
#define KT0 4                   // phase A k-tiles (K=64, real 52)
#define KT1 7                   // phase B k-tiles (K=112, real 101)
#define BPQ 34                  // B pitch (uint4 words per row)

// ---- smem offsets (bytes) ----
#define OFF_WA0 0
#define SZ_WA0  (NTILE*KT0*2*32*16)      // 53248
#define OFF_WA1 (OFF_WA0+SZ_WA0)
#define SZ_WA1  (NTILE*KT1*2*32*16)      // 93184
#define OFF_BQ0 (OFF_WA1+SZ_WA1)         // 146432, double-buffered
#define SZ_BQ0  (KT0*4*BPQ*16)           // 8704
#define OFF_BQ1 (OFF_BQ0+2*SZ_BQ0)       // 163840, double-buffered
#define SZ_BQ1  (KT1*4*BPQ*16)           // 15232
#define SMEM_BYTES (OFF_BQ1+2*SZ_BQ1)    // 194304

#define B0W (SZ_BQ0/16)
#define B1W (SZ_BQ1/16)
#define B0H (SZ_BQ0/2)
#define B1H (SZ_BQ1/2)

__device__ __forceinline__ float tanha(float z) {
    float r; asm("tanh.approx.f32 %0, %1;" : "=f"(r) : "f"(z)); return r;
}
__device__ __forceinline__ float sigf(float z) {
    return fmaf(0.5f, tanha(0.5f * z), 0.5f);
}
__device__ __forceinline__ unsigned short us16(float f) {
    return __bfloat16_as_ushort(__float2bfloat16(f));
}
__device__ __forceinline__ uint32_t pkbf(float e, float o) {
    return (uint32_t)us16(e) | ((uint32_t)us16(o) << 16);
}
__device__ __forceinline__ float bfhi(float f) {
    return __bfloat162float(__float2bfloat16(f));
}
__device__ __forceinline__ int bidx16(int k, int n) {
    int k2 = k >> 1, kt = k2 >> 3, rr = k2 & 7;
    return ((kt * 4 + (rr & 3)) * BPQ + n) * 8 + (rr >> 2) * 4 + (k & 1);
}
__device__ __forceinline__ void mma_bf16(float d[4], uint32_t a0, uint32_t a1,
                                         uint32_t a2, uint32_t a3,
                                         uint32_t b0, uint32_t b1) {
    asm volatile(
        "mma.sync.aligned.m16n8k16.row.col.f32.bf16.bf16.f32 "
        "{%0,%1,%2,%3}, {%4,%5,%6,%7}, {%8,%9}, {%0,%1,%2,%3};"
        : "+f"(d[0]), "+f"(d[1]), "+f"(d[2]), "+f"(d[3])
        : "r"(a0), "r"(a1), "r"(a2), "r"(a3), "r"(b0), "r"(b1));
}

// distributed 4x4 transpose over lane bits 2,3: lane quad index g = (lane>>2)&3,
// input v[m] = gate-g value of combo m; output v[m] = gate-m value of combo g.
__device__ __forceinline__ void xpose4(float v0[4], float v1[4], int lane) {
    const int g0 = (lane >> 2) & 1, g1 = (lane >> 3) & 1;
#pragma unroll
    for (int j = 0; j < 2; j++) {
        float s = g0 ? v0[2 * j] : v0[2 * j + 1];
        s = __shfl_xor_sync(0xffffffffu, s, 4);
        if (g0) v0[2 * j] = s; else v0[2 * j + 1] = s;
        float t = g0 ? v1[2 * j] : v1[2 * j + 1];
        t = __shfl_xor_sync(0xffffffffu, t, 4);
        if (g0) v1[2 * j] = t; else v1[2 * j + 1] = t;
    }
#pragma unroll
    for (int j = 0; j < 2; j++) {
        float s = g1 ? v0[j] : v0[j + 2];
        s = __shfl_xor_sync(0xffffffffu, s, 8);
        if (g1) v0[j] = s; else v0[j + 2] = s;
        float t = g1 ? v1[j] : v1[j + 2];
        t = __shfl_xor_sync(0xffffffffu, t, 8);
        if (g1) v1[j] = t; else v1[j + 2] = t;
    }
}

__global__ void __launch_bounds__(NTH, 1)
lstm_kernel(const float* __restrict__ x,
            const float* __restrict__ w_ih0, const float* __restrict__ w_hh0,
            const float* __restrict__ b_ih0, const float* __restrict__ b_hh0,
            const float* __restrict__ w_ih1, const float* __restrict__ w_hh1,
            const float* __restrict__ b_ih1, const float* __restrict__ b_hh1,
            const float* __restrict__ fc_w,  const float* __restrict__ fc_b,
            float* __restrict__ out) {
    extern __shared__ char sm[];
    uint4* WA0 = (uint4*)(sm + OFF_WA0);
    uint4* WA1 = (uint4*)(sm + OFF_WA1);
    uint4* Bq0 = (uint4*)(sm + OFF_BQ0);
    uint4* Bq1 = (uint4*)(sm + OFF_BQ1);
    unsigned short* B0h = (unsigned short*)(sm + OFF_BQ0);
    unsigned short* B1h = (unsigned short*)(sm + OFF_BQ1);

    const int tid = threadIdx.x, lane = tid & 31, w = tid >> 5;
    const int t4 = lane & 3;
    const int b0g = blockIdx.x * NB;
    const int mt = w >> 1;               // M-tile for this warp
    const int half = w & 1;              // N-half
    const int nt0 = 2 * half;            // first n-subtile

    auto wld = [&](int ph, int R, int k) -> float {
        if (R >= 4 * HDIM) return 0.f;
        int u = R >> 2, gate = R & 3, gi = gate * HDIM + u;
        if (ph == 0) {
            if (k < HDIM)      return w_hh0[gi * HDIM + k];
            if (k == HDIM)     return w_ih0[gi];
            if (k == HDIM + 1) return b_ih0[gi] + b_hh0[gi];
            return 0.f;
        } else {
            if (k < HDIM)      return w_ih1[gi * HDIM + k];
            if (k < 2 * HDIM)  return w_hh1[gi * HDIM + k - HDIM];
            if (k == 2 * HDIM) return b_ih1[gi] + b_hh1[gi];
            return 0.f;
        }
    };
    auto wspl = [&](int ph, int R, int k, int term) -> float {
        float f = wld(ph, R, k);
        float fh = bfhi(f);
        return term ? (f - fh) : fh;
    };

    // ---- build A fragments (hi/lo), frag-order packed ----
    for (int i = tid; i < NTILE * (KT0 + KT1) * 2 * 32; i += NTH) {
        int ln = i & 31;
        int rest = i >> 5;
        int term = rest & 1;
        int tile = rest >> 1;
        int ph, mtt, kt;
        if (tile < NTILE * KT0) { ph = 0; mtt = tile / KT0; kt = tile % KT0; }
        else { int tt = tile - NTILE * KT0; ph = 1; mtt = tt / KT1; kt = tt % KT1; }
        int gg = ln >> 2, tt4 = ln & 3;
        int R0 = mtt * 16 + gg, R1 = R0 + 8, k0 = kt * 16;
        uint4 v;
        v.x = pkbf(wspl(ph, R0, k0 + 2 * tt4,     term), wspl(ph, R0, k0 + 2 * tt4 + 1, term));
        v.y = pkbf(wspl(ph, R1, k0 + 2 * tt4,     term), wspl(ph, R1, k0 + 2 * tt4 + 1, term));
        v.z = pkbf(wspl(ph, R0, k0 + 2 * tt4 + 8, term), wspl(ph, R0, k0 + 2 * tt4 + 9, term));
        v.w = pkbf(wspl(ph, R1, k0 + 2 * tt4 + 8, term), wspl(ph, R1, k0 + 2 * tt4 + 9, term));
        if (ph == 0) WA0[((mtt * KT0 + kt) * 2 + term) * 32 + ln] = v;
        else         WA1[((mtt * KT1 + kt) * 2 + term) * 32 + ln] = v;
    }
    // zero all four B buffers (contiguous)
    for (int i = tid; i < (2 * SZ_BQ0 + 2 * SZ_BQ1) / 4; i += NTH)
        ((uint32_t*)(sm + OFF_BQ0))[i] = 0u;
    __syncthreads();
    // bias columns (both buffers) + x(0) -> B0[1], x(1) -> B0[0]
    if (tid < 32) {
        B0h[0 * B0H + bidx16(51, tid)]  = us16(1.0f);
        B0h[1 * B0H + bidx16(51, tid)]  = us16(1.0f);
        B1h[0 * B1H + bidx16(100, tid)] = us16(1.0f);
        B1h[1 * B1H + bidx16(100, tid)] = us16(1.0f);
        float f0 = x[(size_t)(b0g + tid) * TLEN + 0];
        float h0 = bfhi(f0);
        B0h[1 * B0H + bidx16(50, tid)]     = us16(h0);
        B0h[1 * B0H + bidx16(50, tid) + 2] = us16(f0 - h0);
        float f1 = x[(size_t)(b0g + tid) * TLEN + 1];
        float h1 = bfhi(f1);
        B0h[0 * B0H + bidx16(50, tid)]     = us16(h1);
        B0h[0 * B0H + bidx16(50, tid) + 2] = us16(f1 - h1);
    }
    __syncthreads();

    // cell ownership after shuffle transpose:
    // lane = 16U + 4gq + bq; cells: units 4mt+U and 4mt+U+2, batch below
    const int U  = (lane >> 4) & 1;
    const int gq = (lane >> 2) & 3;
    const int bq = lane & 3;
    const int batc = 16 * half + 8 * (gq >> 1) + 2 * bq + (gq & 1);
    const int uuA = 4 * mt + U;
    const int uuB = 4 * mt + U + 2;
    const bool okA = (uuA < HDIM), okB = (uuB < HDIM);

    float c0[2], c1[2], h1v[2];
#pragma unroll
    for (int j = 0; j < 2; j++) { c0[j] = 0.f; c1[j] = 0.f; h1v[j] = 0.f; }

    // process fragments d[2][4] -> gates for the 2 owned cells
    // v0 = unit uuA gates, v1 = unit uuB gates (after xpose4)
#define GATE_SPLIT(dd, vv0, vv1)                                     \
    float vv0[4] = {dd[0][0], dd[0][1], dd[1][0], dd[1][1]};         \
    float vv1[4] = {dd[0][2], dd[0][3], dd[1][2], dd[1][3]};         \
    xpose4(vv0, vv1, lane);

    // ===== Prologue: phase A only, reads B0[1] -> h0(0) into buf 0 =====
    {
        float d0[2][4];
#pragma unroll
        for (int na = 0; na < 2; na++)
#pragma unroll
            for (int i2 = 0; i2 < 4; i2++) d0[na][i2] = 0.f;
#pragma unroll
        for (int kt = 0; kt < KT0; kt++) {
            uint4 Ah = WA0[((mt * KT0 + kt) * 2 + 0) * 32 + lane];
            uint4 Al = WA0[((mt * KT0 + kt) * 2 + 1) * 32 + lane];
#pragma unroll
            for (int na = 0; na < 2; na++) {
                uint4 bqv = Bq0[1 * B0W + (kt * 4 + t4) * BPQ + (nt0 + na) * 8 + (lane >> 2)];
                mma_bf16(d0[na], Ah.x, Ah.y, Ah.z, Ah.w, bqv.x, bqv.z);
                mma_bf16(d0[na], Ah.x, Ah.y, Ah.z, Ah.w, bqv.y, bqv.w);
                mma_bf16(d0[na], Al.x, Al.y, Al.z, Al.w, bqv.x, bqv.z);
            }
        }
        GATE_SPLIT(d0, v0, v1)
        if (okA) {
            float ig = sigf(v0[0]), fg = sigf(v0[1]), gg = tanha(v0[2]), og = sigf(v0[3]);
            c0[0] = fmaf(fg, c0[0], ig * gg);
            float hn = og * tanha(c0[0]);
            float hh = bfhi(hn);
            unsigned short hb = us16(hn), lb = us16(hn - hh);
            int i0 = bidx16(uuA, batc);
            B0h[0 * B0H + i0] = hb; B0h[0 * B0H + i0 + 2] = lb;
            B1h[0 * B1H + i0] = hb; B1h[0 * B1H + i0 + 2] = lb;
        }
        if (okB) {
            float ig = sigf(v1[0]), fg = sigf(v1[1]), gg = tanha(v1[2]), og = sigf(v1[3]);
            c0[1] = fmaf(fg, c0[1], ig * gg);
            float hn = og * tanha(c0[1]);
            float hh = bfhi(hn);
            unsigned short hb = us16(hn), lb = us16(hn - hh);
            int i0 = bidx16(uuB, batc);
            B0h[0 * B0H + i0] = hb; B0h[0 * B0H + i0 + 2] = lb;
            B1h[0 * B1H + i0] = hb; B1h[0 * B1H + i0 + 2] = lb;
        }
    }
    __syncthreads();

    // ===== Fused main loop: iteration i computes G0(i+1) and G1(i), ONE barrier =====
#pragma unroll 1
    for (int i = 0; i < TLEN - 1; i++) {
        const int cur = i & 1, nxt = cur ^ 1;

        float xv = 0.f;
        if (w == 25 && (i + 2) < TLEN)
            xv = x[(size_t)(b0g + lane) * TLEN + (i + 2)];

        float d0[2][4], d1[2][4];
#pragma unroll
        for (int na = 0; na < 2; na++)
#pragma unroll
            for (int i2 = 0; i2 < 4; i2++) { d0[na][i2] = 0.f; d1[na][i2] = 0.f; }

        // --- all 66 MMAs for this warp back-to-back ---
#pragma unroll
        for (int kt = 0; kt < KT0; kt++) {
            uint4 Ah = WA0[((mt * KT0 + kt) * 2 + 0) * 32 + lane];
            uint4 Al = WA0[((mt * KT0 + kt) * 2 + 1) * 32 + lane];
#pragma unroll
            for (int na = 0; na < 2; na++) {
                uint4 bqv = Bq0[cur * B0W + (kt * 4 + t4) * BPQ + (nt0 + na) * 8 + (lane >> 2)];
                mma_bf16(d0[na], Ah.x, Ah.y, Ah.z, Ah.w, bqv.x, bqv.z);
                mma_bf16(d0[na], Ah.x, Ah.y, Ah.z, Ah.w, bqv.y, bqv.w);
                mma_bf16(d0[na], Al.x, Al.y, Al.z, Al.w, bqv.x, bqv.z);
            }
        }
#pragma unroll
        for (int kt = 0; kt < KT1; kt++) {
            uint4 Ah = WA1[((mt * KT1 + kt) * 2 + 0) * 32 + lane];
            uint4 Al = WA1[((mt * KT1 + kt) * 2 + 1) * 32 + lane];
#pragma unroll
            for (int na = 0; na < 2; na++) {
                uint4 bqv = Bq1[cur * B1W + (kt * 4 + t4) * BPQ + (nt0 + na) * 8 + (lane >> 2)];
                mma_bf16(d1[na], Ah.x, Ah.y, Ah.z, Ah.w, bqv.x, bqv.z);
                mma_bf16(d1[na], Ah.x, Ah.y, Ah.z, Ah.w, bqv.y, bqv.w);
                mma_bf16(d1[na], Al.x, Al.y, Al.z, Al.w, bqv.x, bqv.z);
            }
        }

        // --- epilogue 0: h0(i+1) -> B0[nxt], B1[nxt] (register transpose) ---
        {
            GATE_SPLIT(d0, v0, v1)
            if (okA) {
                float ig = sigf(v0[0]), fg = sigf(v0[1]), gg = tanha(v0[2]), og = sigf(v0[3]);
                c0[0] = fmaf(fg, c0[0], ig * gg);
                float hn = og * tanha(c0[0]);
                float hh = bfhi(hn);
                unsigned short hb = us16(hn), lb = us16(hn - hh);
                int i0 = bidx16(uuA, batc);
                B0h[nxt * B0H + i0] = hb; B0h[nxt * B0H + i0 + 2] = lb;
                B1h[nxt * B1H + i0] = hb; B1h[nxt * B1H + i0 + 2] = lb;
            }
            if (okB) {
                float ig = sigf(v1[0]), fg = sigf(v1[1]), gg = tanha(v1[2]), og = sigf(v1[3]);
                c0[1] = fmaf(fg, c0[1], ig * gg);
                float hn = og * tanha(c0[1]);
                float hh = bfhi(hn);
                unsigned short hb = us16(hn), lb = us16(hn - hh);
                int i0 = bidx16(uuB, batc);
                B0h[nxt * B0H + i0] = hb; B0h[nxt * B0H + i0 + 2] = lb;
                B1h[nxt * B1H + i0] = hb; B1h[nxt * B1H + i0 + 2] = lb;
            }
        }
        // --- epilogue 1: h1(i) -> B1[nxt] ---
        {
            GATE_SPLIT(d1, u0, u1)
            if (okA) {
                float ig = sigf(u0[0]), fg = sigf(u0[1]), gg = tanha(u0[2]), og = sigf(u0[3]);
                c1[0] = fmaf(fg, c1[0], ig * gg);
                float hn = og * tanha(c1[0]);
                h1v[0] = hn;
                float hh = bfhi(hn);
                unsigned short hb = us16(hn), lb = us16(hn - hh);
                int i1 = bidx16(50 + uuA, batc);
                B1h[nxt * B1H + i1] = hb; B1h[nxt * B1H + i1 + 2] = lb;
            }
            if (okB) {
                float ig = sigf(u1[0]), fg = sigf(u1[1]), gg = tanha(u1[2]), og = sigf(u1[3]);
                c1[1] = fmaf(fg, c1[1], ig * gg);
                float hn = og * tanha(c1[1]);
                h1v[1] = hn;
                float hh = bfhi(hn);
                unsigned short hb = us16(hn), lb = us16(hn - hh);
                int i1 = bidx16(50 + uuB, batc);
                B1h[nxt * B1H + i1] = hb; B1h[nxt * B1H + i1 + 2] = lb;
            }
        }
        if (w == 25 && (i + 2) < TLEN) {
            float fh = bfhi(xv);
            B0h[nxt * B0H + bidx16(50, lane)]     = us16(fh);
            B0h[nxt * B0H + bidx16(50, lane) + 2] = us16(xv - fh);
        }
        __syncthreads();
    }

    // ===== Tail: G1(511) from B1[1] -> h1(511) =====
    {
        const int cur = (TLEN - 1) & 1;   // 1
        float d1[2][4];
#pragma unroll
        for (int na = 0; na < 2; na++)
#pragma unroll
            for (int i2 = 0; i2 < 4; i2++) d1[na][i2] = 0.f;
#pragma unroll
        for (int kt = 0; kt < KT1; kt++) {
            uint4 Ah = WA1[((mt * KT1 + kt) * 2 + 0) * 32 + lane];
            uint4 Al = WA1[((mt * KT1 + kt) * 2 + 1) * 32 + lane];
#pragma unroll
            for (int na = 0; na < 2; na++) {
                uint4 bqv = Bq1[cur * B1W + (kt * 4 + t4) * BPQ + (nt0 + na) * 8 + (lane >> 2)];
                mma_bf16(d1[na], Ah.x, Ah.y, Ah.z, Ah.w, bqv.x, bqv.z);
                mma_bf16(d1[na], Ah.x, Ah.y, Ah.z, Ah.w, bqv.y, bqv.w);
                mma_bf16(d1[na], Al.x, Al.y, Al.z, Al.w, bqv.x, bqv.z);
            }
        }
        GATE_SPLIT(d1, u0, u1)
        if (okA) {
            float ig = sigf(u0[0]), fg = sigf(u0[1]), gg = tanha(u0[2]), og = sigf(u0[3]);
            c1[0] = fmaf(fg, c1[0], ig * gg);
            h1v[0] = og * tanha(c1[0]);
        }
        if (okB) {
            float ig = sigf(u1[0]), fg = sigf(u1[1]), gg = tanha(u1[2]), og = sigf(u1[3]);
            c1[1] = fmaf(fg, c1[1], ig * gg);
            h1v[1] = og * tanha(c1[1]);
        }
    }
    __syncthreads();

    // ===== FC epilogue: out[b] = fc_w . h1(511)[b] + fc_b =====
    {
        float* red = (float*)(sm + OFF_BQ0);   // reuse B0 buffers as [u][batch]
        if (okA) red[uuA * 32 + batc] = fc_w[uuA] * h1v[0];
        if (okB) red[uuB * 32 + batc] = fc_w[uuB] * h1v[1];
        __syncthreads();
        if (tid < 32) {
            float s = fc_b[0];
#pragma unroll 10
            for (int k = 0; k < HDIM; k++) s += red[k * 32 + tid];
            out[b0g + tid] = s;
        }
    }
}

extern "C" void kernel_launch(void* const* d_in, const int* in_sizes, int n_in,
                              void* d_out, int out_size) {
    const float* x     = (const float*)d_in[0];
    const float* w_ih0 = (const float*)d_in[1];
    const float* w_hh0 = (const float*)d_in[2];
    const float* b_ih0 = (const float*)d_in[3];
    const float* b_hh0 = (const float*)d_in[4];
    const float* w_ih1 = (const float*)d_in[5];
    const float* w_hh1 = (const float*)d_in[6];
    const float* b_ih1 = (const float*)d_in[7];
    const float* b_hh1 = (const float*)d_in[8];
    const float* fc_w  = (const float*)d_in[9];
    const float* fc_b  = (const float*)d_in[10];
    float* out = (float*)d_out;

    cudaFuncSetAttribute(lstm_kernel, cudaFuncAttributeMaxDynamicSharedMemorySize,
                         SMEM_BYTES);
    lstm_kernel<<<NCTA, NTH, SMEM_BYTES>>>(x, w_ih0, w_hh0, b_ih0, b_hh0,
                                           w_ih1, w_hh1, b_ih1, b_hh1,
                                           fc_w, fc_b, out);
}

// round 16
// speedup vs baseline: 1.7103x; 1.3661x over previous
#include <cuda_runtime.h>
#include <cuda_fp16.h>
#include <cstdint>

#define HDIM 50
#define TLEN 512
#define NB 32
#define NWARP 26
#define NTH (NWARP*32)          // 832
#define NTILE 13                // M-tiles (208 rows)
#define NCTA 128
#define KT0 4                   // phase A k-tiles (K=64, real 52)
#define KT1 7                   // phase B k-tiles (K=112, real 101)
#define BP2 17                  // uint4 per B row (16 + 1 pad)

// ---- smem offsets (bytes) ----
#define OFF_WA0 0
#define SZ_WA0  (NTILE*KT0*32*16)        // 26624
#define OFF_WA1 (OFF_WA0+SZ_WA0)
#define SZ_WA1  (NTILE*KT1*32*16)        // 46592
#define OFF_BQ0 (OFF_WA1+SZ_WA1)         // 73216, double-buffered
#define SZ_BQ0  (KT0*4*BP2*16)           // 4352
#define OFF_BQ1 (OFF_BQ0+2*SZ_BQ0)       // 81920, double-buffered
#define SZ_BQ1  (KT1*4*BP2*16)           // 7616
#define SMEM_BYTES (OFF_BQ1+2*SZ_BQ1)    // 97152

#define B0W (SZ_BQ0/16)         // uint4 per B0 buffer
#define B1W (SZ_BQ1/16)
#define B0H (SZ_BQ0/2)          // u16 per B0 buffer
#define B1H (SZ_BQ1/2)

__device__ __forceinline__ float tanha(float z) {
    float r; asm("tanh.approx.f32 %0, %1;" : "=f"(r) : "f"(z)); return r;
}
__device__ __forceinline__ float sigf(float z) {
    return fmaf(0.5f, tanha(0.5f * z), 0.5f);
}
__device__ __forceinline__ unsigned short ush(float f) {
    __half h = __float2half(f);
    return __half_as_ushort(h);
}
__device__ __forceinline__ uint32_t pkh(float e, float o) {
    return (uint32_t)ush(e) | ((uint32_t)ush(o) << 16);
}
// u16 index of element (k, n) within one B buffer (f16 single-term layout)
__device__ __forceinline__ int bidxh(int k, int n) {
    int rr = (k >> 1) & 7, kt = k >> 4;
    int row = kt * 4 + (rr & 3);
    int u4 = row * BP2 + ((n >> 4) & 1) * 8 + (n & 7);
    return u4 * 8 + ((n >> 3) & 1) * 4 + (rr >> 2) * 2 + (k & 1);
}
__device__ __forceinline__ void mma_f16(float d[4], uint32_t a0, uint32_t a1,
                                        uint32_t a2, uint32_t a3,
                                        uint32_t b0, uint32_t b1) {
    asm volatile(
        "mma.sync.aligned.m16n8k16.row.col.f32.f16.f16.f32 "
        "{%0,%1,%2,%3}, {%4,%5,%6,%7}, {%8,%9}, {%0,%1,%2,%3};"
        : "+f"(d[0]), "+f"(d[1]), "+f"(d[2]), "+f"(d[3])
        : "r"(a0), "r"(a1), "r"(a2), "r"(a3), "r"(b0), "r"(b1));
}

// distributed 4x4 transpose over lane bits 2,3 (identical to R15)
__device__ __forceinline__ void xpose4(float v0[4], float v1[4], int lane) {
    const int g0 = (lane >> 2) & 1, g1 = (lane >> 3) & 1;
#pragma unroll
    for (int j = 0; j < 2; j++) {
        float s = g0 ? v0[2 * j] : v0[2 * j + 1];
        s = __shfl_xor_sync(0xffffffffu, s, 4);
        if (g0) v0[2 * j] = s; else v0[2 * j + 1] = s;
        float t = g0 ? v1[2 * j] : v1[2 * j + 1];
        t = __shfl_xor_sync(0xffffffffu, t, 4);
        if (g0) v1[2 * j] = t; else v1[2 * j + 1] = t;
    }
#pragma unroll
    for (int j = 0; j < 2; j++) {
        float s = g1 ? v0[j] : v0[j + 2];
        s = __shfl_xor_sync(0xffffffffu, s, 8);
        if (g1) v0[j] = s; else v0[j + 2] = s;
        float t = g1 ? v1[j] : v1[j + 2];
        t = __shfl_xor_sync(0xffffffffu, t, 8);
        if (g1) v1[j] = t; else v1[j + 2] = t;
    }
}

__global__ void __launch_bounds__(NTH, 1)
lstm_kernel(const float* __restrict__ x,
            const float* __restrict__ w_ih0, const float* __restrict__ w_hh0,
            const float* __restrict__ b_ih0, const float* __restrict__ b_hh0,
            const float* __restrict__ w_ih1, const float* __restrict__ w_hh1,
            const float* __restrict__ b_ih1, const float* __restrict__ b_hh1,
            const float* __restrict__ fc_w,  const float* __restrict__ fc_b,
            float* __restrict__ out) {
    extern __shared__ char sm[];
    uint4* WA0 = (uint4*)(sm + OFF_WA0);
    uint4* WA1 = (uint4*)(sm + OFF_WA1);
    uint4* Bq0 = (uint4*)(sm + OFF_BQ0);
    uint4* Bq1 = (uint4*)(sm + OFF_BQ1);
    unsigned short* B0h = (unsigned short*)(sm + OFF_BQ0);
    unsigned short* B1h = (unsigned short*)(sm + OFF_BQ1);

    const int tid = threadIdx.x, lane = tid & 31, w = tid >> 5;
    const int t4 = lane & 3;
    const int b0g = blockIdx.x * NB;
    const int mt = w >> 1;               // M-tile for this warp
    const int half = w & 1;              // N-half

    auto wld = [&](int ph, int R, int k) -> float {
        if (R >= 4 * HDIM) return 0.f;
        int u = R >> 2, gate = R & 3, gi = gate * HDIM + u;
        if (ph == 0) {
            if (k < HDIM)      return w_hh0[gi * HDIM + k];
            if (k == HDIM)     return w_ih0[gi];
            if (k == HDIM + 1) return b_ih0[gi] + b_hh0[gi];
            return 0.f;
        } else {
            if (k < HDIM)      return w_ih1[gi * HDIM + k];
            if (k < 2 * HDIM)  return w_hh1[gi * HDIM + k - HDIM];
            if (k == 2 * HDIM) return b_ih1[gi] + b_hh1[gi];
            return 0.f;
        }
    };

    // ---- build A fragments (single fp16), frag-order packed ----
    for (int i = tid; i < NTILE * (KT0 + KT1) * 32; i += NTH) {
        int ln = i & 31;
        int tile = i >> 5;
        int ph, mtt, kt;
        if (tile < NTILE * KT0) { ph = 0; mtt = tile / KT0; kt = tile % KT0; }
        else { int tt = tile - NTILE * KT0; ph = 1; mtt = tt / KT1; kt = tt % KT1; }
        int gg = ln >> 2, tt4 = ln & 3;
        int R0 = mtt * 16 + gg, R1 = R0 + 8, k0 = kt * 16;
        uint4 v;
        v.x = pkh(wld(ph, R0, k0 + 2 * tt4),     wld(ph, R0, k0 + 2 * tt4 + 1));
        v.y = pkh(wld(ph, R1, k0 + 2 * tt4),     wld(ph, R1, k0 + 2 * tt4 + 1));
        v.z = pkh(wld(ph, R0, k0 + 2 * tt4 + 8), wld(ph, R0, k0 + 2 * tt4 + 9));
        v.w = pkh(wld(ph, R1, k0 + 2 * tt4 + 8), wld(ph, R1, k0 + 2 * tt4 + 9));
        if (ph == 0) WA0[(mtt * KT0 + kt) * 32 + ln] = v;
        else         WA1[(mtt * KT1 + kt) * 32 + ln] = v;
    }
    // zero all four B buffers (contiguous)
    for (int i = tid; i < (2 * SZ_BQ0 + 2 * SZ_BQ1) / 4; i += NTH)
        ((uint32_t*)(sm + OFF_BQ0))[i] = 0u;
    __syncthreads();
    // bias columns (both buffers) + x(0) -> B0[1], x(1) -> B0[0]
    if (tid < 32) {
        B0h[0 * B0H + bidxh(51, tid)]  = ush(1.0f);
        B0h[1 * B0H + bidxh(51, tid)]  = ush(1.0f);
        B1h[0 * B1H + bidxh(100, tid)] = ush(1.0f);
        B1h[1 * B1H + bidxh(100, tid)] = ush(1.0f);
        B0h[1 * B0H + bidxh(50, tid)] = ush(x[(size_t)(b0g + tid) * TLEN + 0]);
        B0h[0 * B0H + bidxh(50, tid)] = ush(x[(size_t)(b0g + tid) * TLEN + 1]);
    }
    __syncthreads();

    // cell ownership after shuffle transpose (identical to R15)
    const int U  = (lane >> 4) & 1;
    const int gq = (lane >> 2) & 3;
    const int bq = lane & 3;
    const int batc = 16 * half + 8 * (gq >> 1) + 2 * bq + (gq & 1);
    const int uuA = 4 * mt + U;
    const int uuB = 4 * mt + U + 2;
    const bool okA = (uuA < HDIM), okB = (uuB < HDIM);

    float c0[2], c1[2], h1v[2];
#pragma unroll
    for (int j = 0; j < 2; j++) { c0[j] = 0.f; c1[j] = 0.f; h1v[j] = 0.f; }

#define GATE_SPLIT(dd, vv0, vv1)                                     \
    float vv0[4] = {dd[0][0], dd[0][1], dd[1][0], dd[1][1]};         \
    float vv1[4] = {dd[0][2], dd[0][3], dd[1][2], dd[1][3]};         \
    xpose4(vv0, vv1, lane);

    // B load address for this lane: one uint4 serves both n-subtiles
    const int bcol8 = half * 8 + (lane >> 2);

    // ===== Prologue: phase A only, reads B0[1] -> h0(0) into buf 0 =====
    {
        float d0[2][4];
#pragma unroll
        for (int na = 0; na < 2; na++)
#pragma unroll
            for (int i2 = 0; i2 < 4; i2++) d0[na][i2] = 0.f;
#pragma unroll
        for (int kt = 0; kt < KT0; kt++) {
            uint4 Ah = WA0[(mt * KT0 + kt) * 32 + lane];
            uint4 bqv = Bq0[1 * B0W + (kt * 4 + t4) * BP2 + bcol8];
            mma_f16(d0[0], Ah.x, Ah.y, Ah.z, Ah.w, bqv.x, bqv.y);
            mma_f16(d0[1], Ah.x, Ah.y, Ah.z, Ah.w, bqv.z, bqv.w);
        }
        GATE_SPLIT(d0, v0, v1)
        if (okA) {
            float ig = sigf(v0[0]), fg = sigf(v0[1]), gg = tanha(v0[2]), og = sigf(v0[3]);
            c0[0] = fmaf(fg, c0[0], ig * gg);
            float hn = og * tanha(c0[0]);
            unsigned short hb = ush(hn);
            int i0 = bidxh(uuA, batc);
            B0h[0 * B0H + i0] = hb;
            B1h[0 * B1H + i0] = hb;
        }
        if (okB) {
            float ig = sigf(v1[0]), fg = sigf(v1[1]), gg = tanha(v1[2]), og = sigf(v1[3]);
            c0[1] = fmaf(fg, c0[1], ig * gg);
            float hn = og * tanha(c0[1]);
            unsigned short hb = ush(hn);
            int i0 = bidxh(uuB, batc);
            B0h[0 * B0H + i0] = hb;
            B1h[0 * B1H + i0] = hb;
        }
    }
    __syncthreads();

    // ===== Fused main loop: iteration i computes G0(i+1) and G1(i), ONE barrier =====
#pragma unroll 1
    for (int i = 0; i < TLEN - 1; i++) {
        const int cur = i & 1, nxt = cur ^ 1;

        float xv = 0.f;
        if (w == 25 && (i + 2) < TLEN)
            xv = x[(size_t)(b0g + lane) * TLEN + (i + 2)];

        float d0[2][4], d1[2][4];
#pragma unroll
        for (int na = 0; na < 2; na++)
#pragma unroll
            for (int i2 = 0; i2 < 4; i2++) { d0[na][i2] = 0.f; d1[na][i2] = 0.f; }

        // --- all 22 MMAs for this warp back-to-back ---
#pragma unroll
        for (int kt = 0; kt < KT0; kt++) {
            uint4 Ah = WA0[(mt * KT0 + kt) * 32 + lane];
            uint4 bqv = Bq0[cur * B0W + (kt * 4 + t4) * BP2 + bcol8];
            mma_f16(d0[0], Ah.x, Ah.y, Ah.z, Ah.w, bqv.x, bqv.y);
            mma_f16(d0[1], Ah.x, Ah.y, Ah.z, Ah.w, bqv.z, bqv.w);
        }
#pragma unroll
        for (int kt = 0; kt < KT1; kt++) {
            uint4 Ah = WA1[(mt * KT1 + kt) * 32 + lane];
            uint4 bqv = Bq1[cur * B1W + (kt * 4 + t4) * BP2 + bcol8];
            mma_f16(d1[0], Ah.x, Ah.y, Ah.z, Ah.w, bqv.x, bqv.y);
            mma_f16(d1[1], Ah.x, Ah.y, Ah.z, Ah.w, bqv.z, bqv.w);
        }

        // --- epilogue 0: h0(i+1) -> B0[nxt], B1[nxt] (register transpose) ---
        {
            GATE_SPLIT(d0, v0, v1)
            if (okA) {
                float ig = sigf(v0[0]), fg = sigf(v0[1]), gg = tanha(v0[2]), og = sigf(v0[3]);
                c0[0] = fmaf(fg, c0[0], ig * gg);
                float hn = og * tanha(c0[0]);
                unsigned short hb = ush(hn);
                int i0 = bidxh(uuA, batc);
                B0h[nxt * B0H + i0] = hb;
                B1h[nxt * B1H + i0] = hb;
            }
            if (okB) {
                float ig = sigf(v1[0]), fg = sigf(v1[1]), gg = tanha(v1[2]), og = sigf(v1[3]);
                c0[1] = fmaf(fg, c0[1], ig * gg);
                float hn = og * tanha(c0[1]);
                unsigned short hb = ush(hn);
                int i0 = bidxh(uuB, batc);
                B0h[nxt * B0H + i0] = hb;
                B1h[nxt * B1H + i0] = hb;
            }
        }
        // --- epilogue 1: h1(i) -> B1[nxt] ---
        {
            GATE_SPLIT(d1, u0, u1)
            if (okA) {
                float ig = sigf(u0[0]), fg = sigf(u0[1]), gg = tanha(u0[2]), og = sigf(u0[3]);
                c1[0] = fmaf(fg, c1[0], ig * gg);
                float hn = og * tanha(c1[0]);
                h1v[0] = hn;
                B1h[nxt * B1H + bidxh(50 + uuA, batc)] = ush(hn);
            }
            if (okB) {
                float ig = sigf(u1[0]), fg = sigf(u1[1]), gg = tanha(u1[2]), og = sigf(u1[3]);
                c1[1] = fmaf(fg, c1[1], ig * gg);
                float hn = og * tanha(c1[1]);
                h1v[1] = hn;
                B1h[nxt * B1H + bidxh(50 + uuB, batc)] = ush(hn);
            }
        }
        if (w == 25 && (i + 2) < TLEN)
            B0h[nxt * B0H + bidxh(50, lane)] = ush(xv);
        __syncthreads();
    }

    // ===== Tail: G1(511) from B1[1] -> h1(511) =====
    {
        const int cur = (TLEN - 1) & 1;   // 1
        float d1[2][4];
#pragma unroll
        for (int na = 0; na < 2; na++)
#pragma unroll
            for (int i2 = 0; i2 < 4; i2++) d1[na][i2] = 0.f;
#pragma unroll
        for (int kt = 0; kt < KT1; kt++) {
            uint4 Ah = WA1[(mt * KT1 + kt) * 32 + lane];
            uint4 bqv = Bq1[cur * B1W + (kt * 4 + t4) * BP2 + bcol8];
            mma_f16(d1[0], Ah.x, Ah.y, Ah.z, Ah.w, bqv.x, bqv.y);
            mma_f16(d1[1], Ah.x, Ah.y, Ah.z, Ah.w, bqv.z, bqv.w);
        }
        GATE_SPLIT(d1, u0, u1)
        if (okA) {
            float ig = sigf(u0[0]), fg = sigf(u0[1]), gg = tanha(u0[2]), og = sigf(u0[3]);
            c1[0] = fmaf(fg, c1[0], ig * gg);
            h1v[0] = og * tanha(c1[0]);
        }
        if (okB) {
            float ig = sigf(u1[0]), fg = sigf(u1[1]), gg = tanha(u1[2]), og = sigf(u1[3]);
            c1[1] = fmaf(fg, c1[1], ig * gg);
            h1v[1] = og * tanha(c1[1]);
        }
    }
    __syncthreads();

    // ===== FC epilogue: out[b] = fc_w . h1(511)[b] + fc_b =====
    {
        float* red = (float*)(sm + OFF_WA0);   // reuse weight region as [u][batch]
        if (okA) red[uuA * 32 + batc] = fc_w[uuA] * h1v[0];
        if (okB) red[uuB * 32 + batc] = fc_w[uuB] * h1v[1];
        __syncthreads();
        if (tid < 32) {
            float s = fc_b[0];
#pragma unroll 10
            for (int k = 0; k < HDIM; k++) s += red[k * 32 + tid];
            out[b0g + tid] = s;
        }
    }
}

extern "C" void kernel_launch(void* const* d_in, const int* in_sizes, int n_in,
                              void* d_out, int out_size) {
    const float* x     = (const float*)d_in[0];
    const float* w_ih0 = (const float*)d_in[1];
    const float* w_hh0 = (const float*)d_in[2];
    const float* b_ih0 = (const float*)d_in[3];
    const float* b_hh0 = (const float*)d_in[4];
    const float* w_ih1 = (const float*)d_in[5];
    const float* w_hh1 = (const float*)d_in[6];
    const float* b_ih1 = (const float*)d_in[7];
    const float* b_hh1 = (const float*)d_in[8];
    const float* fc_w  = (const float*)d_in[9];
    const float* fc_b  = (const float*)d_in[10];
    float* out = (float*)d_out;

    cudaFuncSetAttribute(lstm_kernel, cudaFuncAttributeMaxDynamicSharedMemorySize,
                         SMEM_BYTES);
    lstm_kernel<<<NCTA, NTH, SMEM_BYTES>>>(x, w_ih0, w_hh0, b_ih0, b_hh0,
                                           w_ih1, w_hh1, b_ih1, b_hh1,
                                           fc_w, fc_b, out);
}